// round 8
// baseline (speedup 1.0000x reference)
#include <cuda_runtime.h>

typedef unsigned long long ull;

__device__ __forceinline__ ull fma2(ull a, ull b, ull c) {
    ull d;
    asm("fma.rn.f32x2 %0, %1, %2, %3;" : "=l"(d) : "l"(a), "l"(b), "l"(c));
    return d;
}
__device__ __forceinline__ ull pk2(float lo, float hi) {
    ull r;
    asm("mov.b64 %0, {%1, %2};" : "=l"(r) : "f"(lo), "f"(hi));
    return r;
}
__device__ __forceinline__ void unpk(ull v, float& lo, float& hi) {
    asm("mov.b64 {%0, %1}, %2;" : "=f"(lo), "=f"(hi) : "l"(v));
}

#define NWARP 8
#define BPW 2
#define THREADS 256

// dynamic smem layout:
//   [0, 32768)        : W2dup  — 64x64 ull, each = {w,w}
//   then floats F[]:
//     ctxW_s  2880 (45x64, col 63 zero-padded)
//     gcnW_s  49
//     gcnb_s  7
//     ctxb_s  63
//     W1_s    128
//     b1_s    64
//     W3_s    128
//     b3_s    2      (running float total 3321 -> pad to 3322)
//   b2dup 64 ull (512 B)
//   per-warp staging: 8 * 176 floats (xs 64 | cs 48 | adjf 48 | ds 16)
#define SMEM_BYTES (32768 + 3322*4 + 512 + 8*176*4)

__device__ __forceinline__ float zcalc(int hw, const float* __restrict__ xs,
                                       const float* __restrict__ af,
                                       const float* __restrict__ ds,
                                       const float* __restrict__ gw,
                                       const float* __restrict__ gb) {
    int n = hw / 7;
    int f = hw - n * 7;
    // triu index: idx(n,j) = 9n - n(n-1)/2 + (j-n) = rs + j
    int rs = 9 * n - (n * (n - 1)) / 2 - n;
    float dn = ds[n];
    float acc = gb[f];
    for (int j = n; j < 9; ++j) {
        float y = 0.f;
#pragma unroll
        for (int k = 0; k < 7; ++k)
            y = fmaf(xs[j * 7 + k], gw[k * 7 + f], y);
        float a = (j == n) ? 1.f : af[rs + j];
        acc = fmaf(dn * ds[j] * a, y, acc);
    }
    return acc;
}

__global__ __launch_bounds__(THREADS, 1)
void arnet_kernel(const float* __restrict__ x, const int* __restrict__ adj,
                  const float* __restrict__ ctx,
                  const float* __restrict__ gcn_W, const float* __restrict__ gcn_b,
                  const float* __restrict__ ctx_W, const float* __restrict__ ctx_b,
                  const float* __restrict__ W1, const float* __restrict__ b1,
                  const float* __restrict__ W2, const float* __restrict__ b2,
                  const float* __restrict__ W3, const float* __restrict__ b3,
                  float* __restrict__ out, int Btotal) {
    extern __shared__ char smem_raw[];
    ull* W2d = (ull*)smem_raw;
    float* F = (float*)(smem_raw + 32768);
    float* ctxW_s = F;                  // 2880
    float* gcnW_s = ctxW_s + 2880;      // 49
    float* gcnb_s = gcnW_s + 49;        // 7
    float* ctxb_s = gcnb_s + 7;         // 63
    float* W1_s   = ctxb_s + 63;        // 128
    float* b1_s   = W1_s + 128;         // 64
    float* W3_s   = b1_s + 64;          // 128
    float* b3_s   = W3_s + 128;         // 2
    ull*   b2d    = (ull*)(F + 3322);   // 64 ull
    float* stage  = (float*)(b2d + 64);

    int tid = threadIdx.x;

    // ---- cooperative weight preload ----
    for (int i = tid; i < 4096; i += THREADS) {
        float w = W2[i];
        W2d[i] = pk2(w, w);
    }
    for (int i = tid; i < 45 * 64; i += THREADS) {
        int k = i >> 6, hw = i & 63;
        ctxW_s[i] = (hw < 63) ? ctx_W[k * 63 + hw] : 0.f;
    }
    if (tid < 49)  gcnW_s[tid] = gcn_W[tid];
    if (tid < 7)   gcnb_s[tid] = gcn_b[tid];
    if (tid < 63)  ctxb_s[tid] = ctx_b[tid];
    if (tid < 128) W1_s[tid] = W1[tid];
    if (tid < 64) {
        b1_s[tid] = b1[tid];
        float v = b2[tid];
        b2d[tid] = pk2(v, v);
    }
    if (tid < 128) W3_s[tid] = W3[tid];
    if (tid < 2)   b3_s[tid] = b3[tid];
    __syncthreads();

    int warp = tid >> 5;
    int lane = tid & 31;
    float* xs = stage + warp * 176;
    float* cs = xs + 64;
    float* af = cs + 48;
    float* ds = af + 48;

    int hw0 = 2 * lane;
    int hw1 = hw0 + 1;          // hw1 == 63 on lane 31 -> padded, not stored
    bool has1 = (hw1 < 63);

    for (int it = 0; it < BPW; ++it) {
        int b = (blockIdx.x * NWARP + warp) * BPW + it;
        if (b >= Btotal) break;

        // ---- stage this batch (warp-local) ----
        // NOTE: strided loops — 63 and 45 both exceed warp width.
        for (int i = lane; i < 63; i += 32) xs[i] = x[b * 63 + i];
        for (int i = lane; i < 45; i += 32) {
            cs[i] = ctx[b * 45 + i];
            af[i] = (adj[b * 45 + i] > 0) ? 1.f : 0.f;
        }
        __syncwarp();
        if (lane < 9) {
            int rstart = 9 * lane - (lane * (lane - 1)) / 2;
            float deg = 1.f;
            for (int j = lane + 1; j < 9; ++j)
                deg += af[rstart + (j - lane)];
            ds[lane] = rsqrtf(deg);
        }
        __syncwarp();

        // ---- context branch: c = relu(cs @ ctxW + ctxb), packed over hw pair ----
        ull cacc = pk2(ctxb_s[hw0], has1 ? ctxb_s[hw1] : 0.f);
#pragma unroll
        for (int k = 0; k < 45; ++k) {
            float cv = cs[k];
            ull wv = *(const ull*)(ctxW_s + k * 64 + hw0);   // 8B-aligned (hw0 even)
            cacc = fma2(pk2(cv, cv), wv, cacc);
        }
        float c0, c1;
        unpk(cacc, c0, c1);
        c0 = fmaxf(c0, 0.f);
        c1 = has1 ? fmaxf(c1, 0.f) : 0.f;

        // ---- GCN branch ----
        float z0 = zcalc(hw0, xs, af, ds, gcnW_s, gcnb_s);
        float z1 = has1 ? zcalc(hw1, xs, af, ds, gcnW_s, gcnb_s) : 0.f;

        // ---- layer 1: h1[o] = relu(W1[o,0]*z + W1[o,1]*c + b1[o]) ----
        ull h1p[64];
#pragma unroll
        for (int cc = 0; cc < 64; ++cc) {
            float w0 = W1_s[cc * 2], w1 = W1_s[cc * 2 + 1], bb = b1_s[cc];
            float a0 = fmaxf(fmaf(w0, z0, fmaf(w1, c0, bb)), 0.f);
            float a1 = fmaxf(fmaf(w0, z1, fmaf(w1, c1, bb)), 0.f);
            h1p[cc] = pk2(a0, a1);
        }

        // ---- layer 2 (dominant) + layer 3 epilogue fused ----
        float r00 = b3_s[0], r01 = b3_s[0], r10 = b3_s[1], r11 = b3_s[1];
        for (int o = 0; o < 64; o += 4) {
            ull a0 = b2d[o], a1 = b2d[o + 1], a2 = b2d[o + 2], a3 = b2d[o + 3];
            const ull* w0p = W2d + o * 64;
#pragma unroll
            for (int cc = 0; cc < 64; ++cc) {
                ull h = h1p[cc];
                a0 = fma2(h, w0p[cc], a0);
                a1 = fma2(h, w0p[64 + cc], a1);
                a2 = fma2(h, w0p[128 + cc], a2);
                a3 = fma2(h, w0p[192 + cc], a3);
            }
            float lo, hi, w3a, w3b;
            unpk(a0, lo, hi); lo = fmaxf(lo, 0.f); hi = fmaxf(hi, 0.f);
            w3a = W3_s[o];     w3b = W3_s[64 + o];
            r00 = fmaf(w3a, lo, r00); r01 = fmaf(w3a, hi, r01);
            r10 = fmaf(w3b, lo, r10); r11 = fmaf(w3b, hi, r11);

            unpk(a1, lo, hi); lo = fmaxf(lo, 0.f); hi = fmaxf(hi, 0.f);
            w3a = W3_s[o + 1]; w3b = W3_s[64 + o + 1];
            r00 = fmaf(w3a, lo, r00); r01 = fmaf(w3a, hi, r01);
            r10 = fmaf(w3b, lo, r10); r11 = fmaf(w3b, hi, r11);

            unpk(a2, lo, hi); lo = fmaxf(lo, 0.f); hi = fmaxf(hi, 0.f);
            w3a = W3_s[o + 2]; w3b = W3_s[64 + o + 2];
            r00 = fmaf(w3a, lo, r00); r01 = fmaf(w3a, hi, r01);
            r10 = fmaf(w3b, lo, r10); r11 = fmaf(w3b, hi, r11);

            unpk(a3, lo, hi); lo = fmaxf(lo, 0.f); hi = fmaxf(hi, 0.f);
            w3a = W3_s[o + 3]; w3b = W3_s[64 + o + 3];
            r00 = fmaf(w3a, lo, r00); r01 = fmaf(w3a, hi, r01);
            r10 = fmaf(w3b, lo, r10); r11 = fmaf(w3b, hi, r11);
        }

        // ---- store: out[b, 0, hw] and out[b, 1, hw] ----
        float* ob = out + (size_t)b * 126;
        ob[hw0] = r00;
        ob[63 + hw0] = r10;
        if (has1) {
            ob[hw1] = r01;
            ob[63 + hw1] = r11;
        }

        __syncwarp();   // order iteration it's staged-data reads before it+1's writes
    }
}

extern "C" void kernel_launch(void* const* d_in, const int* in_sizes, int n_in,
                              void* d_out, int out_size) {
    const float* x     = (const float*)d_in[0];
    const int*   adj   = (const int*)d_in[1];
    const float* ctx   = (const float*)d_in[2];
    const float* gcn_W = (const float*)d_in[3];
    const float* gcn_b = (const float*)d_in[4];
    const float* ctx_W = (const float*)d_in[5];
    const float* ctx_b = (const float*)d_in[6];
    const float* W1    = (const float*)d_in[7];
    const float* b1    = (const float*)d_in[8];
    const float* W2    = (const float*)d_in[9];
    const float* b2    = (const float*)d_in[10];
    const float* W3    = (const float*)d_in[11];
    const float* b3    = (const float*)d_in[12];
    float* out = (float*)d_out;

    int B = in_sizes[1] / 45;   // adj is (B, 45)
    int blocks = (B + NWARP * BPW - 1) / (NWARP * BPW);

    cudaFuncSetAttribute(arnet_kernel,
                         cudaFuncAttributeMaxDynamicSharedMemorySize, SMEM_BYTES);
    arnet_kernel<<<blocks, THREADS, SMEM_BYTES>>>(
        x, adj, ctx, gcn_W, gcn_b, ctx_W, ctx_b,
        W1, b1, W2, b2, W3, b3, out, B);
}